// round 14
// baseline (speedup 1.0000x reference)
#include <cuda_runtime.h>
#include <cuda_fp16.h>
#include <cstdint>

#define B_     2
#define L_     2048
#define QD_    1024
#define H_     16
#define D_     64
#define INNER_ 1024
#define M_     4096
#define NF_    3072

typedef __half fp16;

// ---------------------------------------------------------------------------
// Scratch (__device__ globals; allocation-free rule)
// ---------------------------------------------------------------------------
__device__ fp16 g_x [M_ * QD_];                       // single fp16 activations
__device__ fp16 g_Wh[NF_ * QD_], g_Wl[NF_ * QD_];     // [Wq ; Wkv] hi/lo
__device__ fp16 g_Ph[QD_ * INNER_], g_Pl[QD_ * INNER_];
__device__ fp16 g_Qh[M_ * INNER_], g_Ql[M_ * INNER_]; // [b*H+h][l][d]
__device__ fp16 g_K [M_ * INNER_];                    // single fp16
__device__ fp16 g_Vh[M_ * INNER_], g_Vl[M_ * INNER_];
__device__ fp16 g_Oh[M_ * INNER_], g_Ol[M_ * INNER_]; // [m][h*64+d]

// ---------------------------------------------------------------------------
// Baseline-PTX helpers
// ---------------------------------------------------------------------------
__device__ __forceinline__ uint32_t smem_u32(const void* p) {
    uint32_t a;
    asm("{ .reg .u64 t; cvta.to.shared.u64 t, %1; cvt.u32.u64 %0, t; }"
        : "=r"(a) : "l"(p));
    return a;
}
__device__ __forceinline__ void cpa16(uint32_t s, const void* g) {
    asm volatile("cp.async.cg.shared.global [%0], [%1], 16;" :: "r"(s), "l"(g));
}
#define CP_COMMIT() asm volatile("cp.async.commit_group;" ::: "memory")
#define CP_WAIT(n)  asm volatile("cp.async.wait_group %0;" :: "n"(n) : "memory")

__device__ __forceinline__ void ldx4(uint32_t r[4], uint32_t a) {
    asm volatile("ldmatrix.sync.aligned.m8n8.x4.shared.b16 {%0,%1,%2,%3}, [%4];"
        : "=r"(r[0]), "=r"(r[1]), "=r"(r[2]), "=r"(r[3]) : "r"(a));
}
__device__ __forceinline__ void ldx4t(uint32_t r[4], uint32_t a) {
    asm volatile("ldmatrix.sync.aligned.m8n8.x4.trans.shared.b16 {%0,%1,%2,%3}, [%4];"
        : "=r"(r[0]), "=r"(r[1]), "=r"(r[2]), "=r"(r[3]) : "r"(a));
}
__device__ __forceinline__ void mma16816(float c[4], const uint32_t a[4],
                                         const uint32_t b[2]) {
    asm volatile(
        "mma.sync.aligned.m16n8k16.row.col.f32.f16.f16.f32 "
        "{%0,%1,%2,%3}, {%4,%5,%6,%7}, {%8,%9}, {%0,%1,%2,%3};"
        : "+f"(c[0]), "+f"(c[1]), "+f"(c[2]), "+f"(c[3])
        : "r"(a[0]), "r"(a[1]), "r"(a[2]), "r"(a[3]), "r"(b[0]), "r"(b[1]));
}
__device__ __forceinline__ uint32_t swz(uint32_t o) { return o ^ ((o >> 3) & 0x70); }

__device__ __forceinline__ float ex2f(float x) {
    float y;
    asm("ex2.approx.f32 %0, %1;" : "=f"(y) : "f"(x));
    return y;
}
__device__ __forceinline__ uint32_t packh2(float x, float y) {
    __half2 h = __float22half2_rn(make_float2(x, y));
    return reinterpret_cast<uint32_t&>(h);
}
__device__ __forceinline__ float2 unpackh2(uint32_t u) {
    return __half22float2(reinterpret_cast<__half2&>(u));
}
__device__ __forceinline__ void store_hl(fp16* dh, fp16* dl, size_t idx,
                                         float v0, float v1) {
    fp16 h0 = __float2half_rn(v0), h1 = __float2half_rn(v1);
    float l0 = v0 - __half2float(h0), l1 = v1 - __half2float(h1);
    __half2 hh = __halves2half2(h0, h1);
    *reinterpret_cast<uint32_t*>(dh + idx) = reinterpret_cast<uint32_t&>(hh);
    *reinterpret_cast<uint32_t*>(dl + idx) = packh2(l0, l1);
}

// ---------------------------------------------------------------------------
// Fused prologue: x cvt + Wq/Wkv split + Wp split, one launch
// ---------------------------------------------------------------------------
__device__ __forceinline__ void split4(const float* __restrict__ s,
                                       fp16* hi, fp16* lo, size_t i4)
{
    float4 v = reinterpret_cast<const float4*>(s)[i4];
    store_hl(hi, lo, i4 * 4,     v.x, v.y);
    store_hl(hi, lo, i4 * 4 + 2, v.z, v.w);
}

__global__ __launch_bounds__(256) void prep_kernel(
    const float* __restrict__ x,  const float* __restrict__ Wq,
    const float* __restrict__ Wkv, const float* __restrict__ Wp)
{
    const int bid = blockIdx.x, tid = threadIdx.x;
    if (bid < 4096) {                       // x: 1M float4 -> fp16
        size_t i = (size_t)bid * 256 + tid;
        float4 v = reinterpret_cast<const float4*>(x)[i];
        uint2 o = make_uint2(packh2(v.x, v.y), packh2(v.z, v.w));
        *reinterpret_cast<uint2*>(g_x + i * 4) = o;
    } else if (bid < 5120) {                // Wq
        size_t i = (size_t)(bid - 4096) * 256 + tid;
        split4(Wq, g_Wh, g_Wl, i);
    } else if (bid < 7168) {                // Wkv, offset 1M elems
        size_t i = (size_t)(bid - 5120) * 256 + tid;
        float4 v = reinterpret_cast<const float4*>(Wkv)[i];
        size_t o = (size_t)INNER_ * QD_ + i * 4;
        store_hl(g_Wh, g_Wl, o,     v.x, v.y);
        store_hl(g_Wh, g_Wl, o + 2, v.z, v.w);
    } else {                                // Wp
        size_t i = (size_t)(bid - 7168) * 256 + tid;
        split4(Wp, g_Ph, g_Pl, i);
    }
}

// ---------------------------------------------------------------------------
// QKV GEMM mainloop: CTA 256m x 64n, 8 warps, warp tile m32 x n64 (R13 proven)
// ---------------------------------------------------------------------------
#define QSTAGE 49152
#define NCH    16

__device__ __forceinline__ void gemm_a1b2_m32(
    const fp16* __restrict__ A,
    const fp16* __restrict__ Bh, const fp16* __restrict__ Bl,
    int m0, int n0, char* smem, float c[16][4])
{
    const int tid = threadIdx.x;
    const int lane = tid & 31, w = tid >> 5;
    const uint32_t sb = smem_u32(smem);

    const int arow = (lane & 7) + ((lane >> 3) & 1) * 8;
    const int acb  = (lane >> 4) * 16;
    const int brow = (lane & 7) + ((lane >> 4) & 1) * 8;
    const int bcb  = ((lane >> 3) & 1) * 16;

    const fp16* Ap  = A  + (size_t)m0 * QD_;
    const fp16* Bhp = Bh + (size_t)n0 * QD_;
    const fp16* Blp = Bl + (size_t)n0 * QD_;

    auto load_stage = [&](int st, int ch) {
        uint32_t base = sb + st * QSTAGE;
        #pragma unroll
        for (int i = 0; i < 8; ++i) {
            int u = tid + i * 256;
            int row = u >> 3, s7 = u & 7;
            cpa16(base + swz(row * 128 + s7 * 16),
                  Ap + (size_t)row * QD_ + ch * 64 + s7 * 8);
        }
        #pragma unroll
        for (int i = 0; i < 2; ++i) {
            int u = tid + i * 256;
            int row = u >> 3, s7 = u & 7;
            uint32_t so = swz(row * 128 + s7 * 16);
            cpa16(base + 32768 + so, Bhp + (size_t)row * QD_ + ch * 64 + s7 * 8);
            cpa16(base + 40960 + so, Blp + (size_t)row * QD_ + ch * 64 + s7 * 8);
        }
    };

    load_stage(0, 0); CP_COMMIT();

    for (int ch = 0; ch < NCH; ++ch) {
        CP_WAIT(0);
        __syncthreads();
        if (ch + 1 < NCH) {
            load_stage((ch + 1) & 1, ch + 1);
            CP_COMMIT();
        }

        uint32_t base = sb + (ch & 1) * QSTAGE;
        #pragma unroll
        for (int ks = 0; ks < 4; ++ks) {
            uint32_t a0[4], a1[4];
            ldx4(a0, base + swz((w * 32 +      arow) * 128 + ks * 32 + acb));
            ldx4(a1, base + swz((w * 32 + 16 + arow) * 128 + ks * 32 + acb));
            #pragma unroll
            for (int ng = 0; ng < 4; ++ng) {
                uint32_t bd = base + 32768
                            + swz((ng * 16 + brow) * 128 + ks * 32 + bcb);
                uint32_t bh[4], bl[4];
                ldx4(bh, bd);
                ldx4(bl, bd + 8192);
                mma16816(c[2*ng],       a0, bh);     mma16816(c[2*ng],       a0, bl);
                mma16816(c[2*ng+1],     a0, bh + 2); mma16816(c[2*ng+1],     a0, bl + 2);
                mma16816(c[8 + 2*ng],   a1, bh);     mma16816(c[8 + 2*ng],   a1, bl);
                mma16816(c[8 + 2*ng+1], a1, bh + 2); mma16816(c[8 + 2*ng+1], a1, bl + 2);
            }
        }
    }
}

// ---------------------------------------------------------------------------
// Proj GEMM mainloop (fp16x3, exact): CTA 128m x 64n, 4 warps, m32/warp
// 12 LDSM / 48 MMAs per warp*ks (ratio 4.0). Stage 48K, 2 stages -> 2 CTAs/SM
// ---------------------------------------------------------------------------
#define GSTAGE 49152

__device__ __forceinline__ void gemm_a2b2_m32(
    const fp16* __restrict__ Ah, const fp16* __restrict__ Al,
    const fp16* __restrict__ Bh, const fp16* __restrict__ Bl,
    int m0, int n0, char* smem, float c[16][4])
{
    const int tid = threadIdx.x;
    const int lane = tid & 31, w = tid >> 5;
    const uint32_t sb = smem_u32(smem);

    const int arow = (lane & 7) + ((lane >> 3) & 1) * 8;
    const int acb  = (lane >> 4) * 16;
    const int brow = (lane & 7) + ((lane >> 4) & 1) * 8;
    const int bcb  = ((lane >> 3) & 1) * 16;

    const fp16* Ahp = Ah + (size_t)m0 * QD_;
    const fp16* Alp = Al + (size_t)m0 * QD_;
    const fp16* Bhp = Bh + (size_t)n0 * QD_;
    const fp16* Blp = Bl + (size_t)n0 * QD_;

    auto load_stage = [&](int st, int ch) {
        uint32_t base = sb + st * GSTAGE;
        #pragma unroll
        for (int i = 0; i < 8; ++i) {           // A: 128 rows, hi+lo
            int u = tid + i * 128;
            int row = u >> 3, s7 = u & 7;
            uint32_t so = swz(row * 128 + s7 * 16);
            cpa16(base + so,         Ahp + (size_t)row * QD_ + ch * 64 + s7 * 8);
            cpa16(base + 16384 + so, Alp + (size_t)row * QD_ + ch * 64 + s7 * 8);
        }
        #pragma unroll
        for (int i = 0; i < 4; ++i) {           // B: 64 rows, hi+lo
            int u = tid + i * 128;
            int row = u >> 3, s7 = u & 7;
            uint32_t so = swz(row * 128 + s7 * 16);
            cpa16(base + 32768 + so, Bhp + (size_t)row * QD_ + ch * 64 + s7 * 8);
            cpa16(base + 40960 + so, Blp + (size_t)row * QD_ + ch * 64 + s7 * 8);
        }
    };

    load_stage(0, 0); CP_COMMIT();

    for (int ch = 0; ch < NCH; ++ch) {
        CP_WAIT(0);
        __syncthreads();
        if (ch + 1 < NCH) {
            load_stage((ch + 1) & 1, ch + 1);
            CP_COMMIT();
        }

        uint32_t base = sb + (ch & 1) * GSTAGE;
        #pragma unroll
        for (int ks = 0; ks < 4; ++ks) {
            uint32_t ah0[4], ah1[4], al0[4], al1[4];
            uint32_t ad0 = base + swz((w * 32 +      arow) * 128 + ks * 32 + acb);
            uint32_t ad1 = base + swz((w * 32 + 16 + arow) * 128 + ks * 32 + acb);
            ldx4(ah0, ad0); ldx4(al0, ad0 + 16384);
            ldx4(ah1, ad1); ldx4(al1, ad1 + 16384);
            #pragma unroll
            for (int ng = 0; ng < 4; ++ng) {
                uint32_t bd = base + 32768
                            + swz((ng * 16 + brow) * 128 + ks * 32 + bcb);
                uint32_t bh[4], bl[4];
                ldx4(bh, bd);
                ldx4(bl, bd + 8192);
                // per-accumulator order: ah*bh, ah*bl, al*bh (bitwise-preserved)
                mma16816(c[2*ng],       ah0, bh);     mma16816(c[2*ng],       ah0, bl);
                mma16816(c[2*ng],       al0, bh);
                mma16816(c[2*ng+1],     ah0, bh + 2); mma16816(c[2*ng+1],     ah0, bl + 2);
                mma16816(c[2*ng+1],     al0, bh + 2);
                mma16816(c[8 + 2*ng],   ah1, bh);     mma16816(c[8 + 2*ng],   ah1, bl);
                mma16816(c[8 + 2*ng],   al1, bh);
                mma16816(c[8 + 2*ng+1], ah1, bh + 2); mma16816(c[8 + 2*ng+1], ah1, bl + 2);
                mma16816(c[8 + 2*ng+1], al1, bh + 2);
            }
        }
    }
}

// ---------------------------------------------------------------------------
// QKV projection GEMM (x single * W hi/lo) + RMSNorm + RoPE  (R13, unchanged)
// ---------------------------------------------------------------------------
__global__ __launch_bounds__(256, 2) void qkv_mma(
    const float* __restrict__ pe,
    const float* __restrict__ qsc, const float* __restrict__ ksc)
{
    extern __shared__ char smem[];
    const int m0 = blockIdx.x * 256, n0 = blockIdx.y * 64;
    float c[16][4];
    #pragma unroll
    for (int j = 0; j < 16; ++j)
        #pragma unroll
        for (int k = 0; k < 4; ++k) c[j][k] = 0.f;

    gemm_a1b2_m32(g_x, g_Wh, g_Wl, m0, n0, smem, c);

    const int tid = threadIdx.x, lane = tid & 31, w = tid >> 5;
    const int tq = lane & 3, g = lane >> 2;

    const int kind = n0 >> 10;               // 0:Q 1:K 2:V
    const int h = (n0 & 1023) >> 6;
    const float* sc = (kind == 0) ? qsc : ksc;
    const float qm = (kind == 0) ? 0.125f * 1.4426950408889634f : 1.f;

    #pragma unroll
    for (int mi = 0; mi < 2; ++mi)
        #pragma unroll
        for (int half_ = 0; half_ < 2; ++half_) {
            const int m = m0 + w * 32 + mi * 16 + g + half_ * 8;
            const int b = m >> 11, l = m & 2047;
            const size_t obase = ((size_t)(b * H_ + h) * L_ + l) * 64;
            float (*cc)[4] = c + mi * 8;

            if (kind == 2) {
                #pragma unroll
                for (int ni = 0; ni < 8; ++ni) {
                    int d0 = ni * 8 + tq * 2;
                    store_hl(g_Vh, g_Vl, obase + d0,
                             cc[ni][half_ * 2], cc[ni][half_ * 2 + 1]);
                }
            } else {
                float ss = 0.f;
                #pragma unroll
                for (int ni = 0; ni < 8; ++ni) {
                    float v0 = cc[ni][half_ * 2], v1 = cc[ni][half_ * 2 + 1];
                    ss = fmaf(v0, v0, fmaf(v1, v1, ss));
                }
                ss += __shfl_xor_sync(0xffffffffu, ss, 1);
                ss += __shfl_xor_sync(0xffffffffu, ss, 2);
                const float rr = rsqrtf(ss * (1.f / 64.f) + 1e-6f);
                const float* pel = pe + (size_t)l * 128;
                #pragma unroll
                for (int ni = 0; ni < 8; ++ni) {
                    int d0 = ni * 8 + tq * 2;
                    float v0 = cc[ni][half_ * 2]     * rr * sc[d0];
                    float v1 = cc[ni][half_ * 2 + 1] * rr * sc[d0 + 1];
                    float4 p = *reinterpret_cast<const float4*>(pel + (d0 >> 1) * 4);
                    float o0 = (p.x * v0 + p.y * v1) * qm;
                    float o1 = (p.z * v0 + p.w * v1) * qm;
                    if (kind == 0) store_hl(g_Qh, g_Ql, obase + d0, o0, o1);
                    else *reinterpret_cast<uint32_t*>(g_K + obase + d0) = packh2(o0, o1);
                }
            }
        }
}

// ---------------------------------------------------------------------------
// Output projection GEMM (exact fp16x3, m32 warps) + bias
//   grid = (M_/128, QD_/64), 128 threads
// ---------------------------------------------------------------------------
__global__ __launch_bounds__(128, 2) void proj_mma(
    const float* __restrict__ bp, float* __restrict__ out)
{
    extern __shared__ char smem[];
    const int m0 = blockIdx.x * 128, n0 = blockIdx.y * 64;
    float c[16][4];
    #pragma unroll
    for (int j = 0; j < 16; ++j)
        #pragma unroll
        for (int k = 0; k < 4; ++k) c[j][k] = 0.f;

    gemm_a2b2_m32(g_Oh, g_Ol, g_Ph, g_Pl, m0, n0, smem, c);

    const int tid = threadIdx.x, lane = tid & 31, w = tid >> 5;
    const int tq = lane & 3, g = lane >> 2;

    #pragma unroll
    for (int mi = 0; mi < 2; ++mi)
        #pragma unroll
        for (int half_ = 0; half_ < 2; ++half_) {
            const int m = m0 + w * 32 + mi * 16 + g + half_ * 8;
            float (*cc)[4] = c + mi * 8;
            #pragma unroll
            for (int ni = 0; ni < 8; ++ni) {
                int col = n0 + ni * 8 + tq * 2;
                float2 bv = *reinterpret_cast<const float2*>(bp + col);
                float2 o = make_float2(cc[ni][half_ * 2]     + bv.x,
                                       cc[ni][half_ * 2 + 1] + bv.y);
                *reinterpret_cast<float2*>(out + (size_t)m * QD_ + col) = o;
            }
        }
}

// ---------------------------------------------------------------------------
// Flash attention, fp16 HMMA, exp2-domain online softmax
//   CTA = 128 q-rows, 4 warps (m32/warp), 2 CTAs/SM
//   K/V LDSM per MMA halved vs m16. Per-row FP order unchanged.
//   smem: Qh 16K | Ql 16K | 2 stages x (K 8K | Vh 8K | Vl 8K) = 80K
// ---------------------------------------------------------------------------
#define ASTAGE 24576
#define ASMEM  (32768 + 2 * ASTAGE)
#define NIT    32

__global__ __launch_bounds__(128, 2) void attn_mma()
{
    extern __shared__ char smem[];
    const int tid = threadIdx.x, lane = tid & 31, w = tid >> 5;
    const int by = blockIdx.y;
    const int q0 = blockIdx.x * 128;
    const uint32_t sb = smem_u32(smem);

    const fp16* Qhp = g_Qh + ((size_t)by * L_ + q0) * 64;
    const fp16* Qlp = g_Ql + ((size_t)by * L_ + q0) * 64;
    const fp16* Kp  = g_K  + (size_t)by * L_ * 64;
    const fp16* Vhp = g_Vh + (size_t)by * L_ * 64;
    const fp16* Vlp = g_Vl + (size_t)by * L_ * 64;

    const int tq = lane & 3, g = lane >> 2;
    const int arow = (lane & 7) + ((lane >> 3) & 1) * 8;
    const int acb  = (lane >> 4) * 16;
    const int brow = (lane & 7) + ((lane >> 4) & 1) * 8;
    const int bcb  = ((lane >> 3) & 1) * 16;

    auto load_kv = [&](int st, int kt) {
        uint32_t base = sb + 32768 + st * ASTAGE;
        const fp16* srcs[3] = { Kp, Vhp, Vlp };
        #pragma unroll
        for (int mtx = 0; mtx < 3; ++mtx)
            #pragma unroll
            for (int i = 0; i < 4; ++i) {
                int u = tid + i * 128;
                int row = u >> 3, s7 = u & 7;
                cpa16(base + mtx * 8192 + swz(row * 128 + s7 * 16),
                      srcs[mtx] + (size_t)(kt * 64 + row) * 64 + s7 * 8);
            }
    };

    // prologue: Q (128 rows, hi/lo) + KV stage0
    #pragma unroll
    for (int i = 0; i < 8; ++i) {
        int u = tid + i * 128;
        int row = u >> 3, s7 = u & 7;
        uint32_t so = swz(row * 128 + s7 * 16);
        cpa16(sb +         so, Qhp + (size_t)row * 64 + s7 * 8);
        cpa16(sb + 16384 + so, Qlp + (size_t)row * 64 + s7 * 8);
    }
    load_kv(0, 0); CP_COMMIT();

    float o[16][4];
    #pragma unroll
    for (int i = 0; i < 16; ++i)
        #pragma unroll
        for (int j = 0; j < 4; ++j) o[i][j] = 0.f;
    float mr[4], lr[4];
    #pragma unroll
    for (int i = 0; i < 4; ++i) { mr[i] = -1e30f; lr[i] = 0.f; }
    uint32_t qhf[4][2][4], qlf[4][2][4];   // [ks][mi][reg]

    for (int it = 0; it < NIT; ++it) {
        CP_WAIT(0);
        __syncthreads();
        if (it + 1 < NIT) {
            load_kv((it + 1) & 1, it + 1);
            CP_COMMIT();
        }

        if (it == 0) {
            #pragma unroll
            for (int ks = 0; ks < 4; ++ks) {
                uint32_t ad0 = sb + swz((w * 32 +      arow) * 128 + ks * 32 + acb);
                uint32_t ad1 = sb + swz((w * 32 + 16 + arow) * 128 + ks * 32 + acb);
                ldx4(qhf[ks][0], ad0); ldx4(qlf[ks][0], ad0 + 16384);
                ldx4(qhf[ks][1], ad1); ldx4(qlf[ks][1], ad1 + 16384);
            }
        }

        const uint32_t kb = sb + 32768 + (it & 1) * ASTAGE;

        // ---- S = (Qh+Ql) K^T (log2 domain) ----
        float s[16][4];
        #pragma unroll
        for (int i = 0; i < 16; ++i)
            #pragma unroll
            for (int j = 0; j < 4; ++j) s[i][j] = 0.f;

        #pragma unroll
        for (int ks = 0; ks < 4; ++ks)
            #pragma unroll
            for (int ng = 0; ng < 4; ++ng) {
                uint32_t kd = kb + swz((ng * 16 + brow) * 128 + ks * 32 + bcb);
                uint32_t kh[4];
                ldx4(kh, kd);
                #pragma unroll
                for (int mi = 0; mi < 2; ++mi) {
                    mma16816(s[mi*8 + 2*ng],   qhf[ks][mi], kh);
                    mma16816(s[mi*8 + 2*ng],   qlf[ks][mi], kh);
                    mma16816(s[mi*8 + 2*ng+1], qhf[ks][mi], kh + 2);
                    mma16816(s[mi*8 + 2*ng+1], qlf[ks][mi], kh + 2);
                }
            }

        // ---- online softmax (exp2 domain, consistent quantized sums) ----
        uint32_t ph01[2][8], ph23[2][8];
        #pragma unroll
        for (int mi = 0; mi < 2; ++mi) {
            float (*sm)[4] = s + mi * 8;
            float mx0 = -1e30f, mx1 = -1e30f;
            #pragma unroll
            for (int ni = 0; ni < 8; ++ni) {
                mx0 = fmaxf(mx0, fmaxf(sm[ni][0], sm[ni][1]));
                mx1 = fmaxf(mx1, fmaxf(sm[ni][2], sm[ni][3]));
            }
            mx0 = fmaxf(mx0, __shfl_xor_sync(0xffffffffu, mx0, 1));
            mx0 = fmaxf(mx0, __shfl_xor_sync(0xffffffffu, mx0, 2));
            mx1 = fmaxf(mx1, __shfl_xor_sync(0xffffffffu, mx1, 1));
            mx1 = fmaxf(mx1, __shfl_xor_sync(0xffffffffu, mx1, 2));
            const float mn0 = fmaxf(mr[mi*2],   mx0);
            const float mn1 = fmaxf(mr[mi*2+1], mx1);
            const float cr0 = ex2f(mr[mi*2]   - mn0);
            const float cr1 = ex2f(mr[mi*2+1] - mn1);
            mr[mi*2] = mn0; mr[mi*2+1] = mn1;

            float sum0 = 0.f, sum1 = 0.f;
            #pragma unroll
            for (int ni = 0; ni < 8; ++ni) {
                float p0 = ex2f(sm[ni][0] - mn0), p1 = ex2f(sm[ni][1] - mn0);
                float p2 = ex2f(sm[ni][2] - mn1), p3 = ex2f(sm[ni][3] - mn1);
                ph01[mi][ni] = packh2(p0, p1);
                ph23[mi][ni] = packh2(p2, p3);
                float2 q01 = unpackh2(ph01[mi][ni]);
                float2 q23 = unpackh2(ph23[mi][ni]);
                sum0 += q01.x + q01.y;
                sum1 += q23.x + q23.y;
            }
            sum0 += __shfl_xor_sync(0xffffffffu, sum0, 1);
            sum0 += __shfl_xor_sync(0xffffffffu, sum0, 2);
            sum1 += __shfl_xor_sync(0xffffffffu, sum1, 1);
            sum1 += __shfl_xor_sync(0xffffffffu, sum1, 2);
            lr[mi*2]   = lr[mi*2]   * cr0 + sum0;
            lr[mi*2+1] = lr[mi*2+1] * cr1 + sum1;
            float (*om)[4] = o + mi * 8;
            #pragma unroll
            for (int ni = 0; ni < 8; ++ni) {
                om[ni][0] *= cr0; om[ni][1] *= cr0;
                om[ni][2] *= cr1; om[ni][3] *= cr1;
            }
        }

        // ---- O += P̂ (Vh+Vl) ----
        const uint32_t vb = kb + 8192;
        #pragma unroll
        for (int kk = 0; kk < 4; ++kk) {
            uint32_t pa0[4] = { ph01[0][2*kk], ph23[0][2*kk],
                                ph01[0][2*kk+1], ph23[0][2*kk+1] };
            uint32_t pa1[4] = { ph01[1][2*kk], ph23[1][2*kk],
                                ph01[1][2*kk+1], ph23[1][2*kk+1] };
            #pragma unroll
            for (int dg = 0; dg < 4; ++dg) {
                uint32_t vd = vb + swz((kk * 16 + arow) * 128 + dg * 32 + acb);
                uint32_t vh[4], vl[4];
                ldx4t(vh, vd);
                ldx4t(vl, vd + 8192);
                mma16816(o[2*dg],       pa0, vh);
                mma16816(o[2*dg],       pa0, vl);
                mma16816(o[2*dg+1],     pa0, vh + 2);
                mma16816(o[2*dg+1],     pa0, vl + 2);
                mma16816(o[8 + 2*dg],   pa1, vh);
                mma16816(o[8 + 2*dg],   pa1, vl);
                mma16816(o[8 + 2*dg+1], pa1, vh + 2);
                mma16816(o[8 + 2*dg+1], pa1, vl + 2);
            }
        }
    }

    // ---- epilogue ----
    const int b = by >> 4, h = by & 15;
    #pragma unroll
    for (int mi = 0; mi < 2; ++mi)
        #pragma unroll
        for (int half_ = 0; half_ < 2; ++half_) {
            const int l = q0 + w * 32 + mi * 16 + g + half_ * 8;
            const size_t mbase = ((size_t)(b * L_ + l)) * INNER_ + h * 64;
            const float inv = 1.f / lr[mi*2 + half_];
            float (*om)[4] = o + mi * 8;
            #pragma unroll
            for (int ni = 0; ni < 8; ++ni) {
                int d0 = ni * 8 + tq * 2;
                store_hl(g_Oh, g_Ol, mbase + d0,
                         om[ni][half_ * 2] * inv, om[ni][half_ * 2 + 1] * inv);
            }
        }
}

// ---------------------------------------------------------------------------
extern "C" void kernel_launch(void* const* d_in, const int* in_sizes, int n_in,
                              void* d_out, int out_size)
{
    const float* x   = (const float*)d_in[0];
    const float* pe  = (const float*)d_in[1];
    const float* Wq  = (const float*)d_in[2];
    const float* Wkv = (const float*)d_in[3];
    const float* Wp  = (const float*)d_in[4];
    const float* bp  = (const float*)d_in[5];
    const float* qs  = (const float*)d_in[6];
    const float* ks  = (const float*)d_in[7];
    float* out = (float*)d_out;

    cudaFuncSetAttribute(qkv_mma,  cudaFuncAttributeMaxDynamicSharedMemorySize, 2 * QSTAGE);
    cudaFuncSetAttribute(proj_mma, cudaFuncAttributeMaxDynamicSharedMemorySize, 2 * GSTAGE);
    cudaFuncSetAttribute(attn_mma, cudaFuncAttributeMaxDynamicSharedMemorySize, ASMEM);

    prep_kernel<<<8192, 256>>>(x, Wq, Wkv, Wp);
    qkv_mma<<<dim3(M_ / 256, NF_ / 64), 256, 2 * QSTAGE>>>(pe, qs, ks);
    attn_mma<<<dim3(L_ / 128, B_ * H_), 128, ASMEM>>>();
    proj_mma<<<dim3(M_ / 128, QD_ / 64), 128, 2 * GSTAGE>>>(bp, out);
}

// round 15
// speedup vs baseline: 1.1398x; 1.1398x over previous
#include <cuda_runtime.h>
#include <cuda_fp16.h>
#include <cstdint>

#define B_     2
#define L_     2048
#define QD_    1024
#define H_     16
#define D_     64
#define INNER_ 1024
#define M_     4096
#define NF_    3072

typedef __half fp16;

// ---------------------------------------------------------------------------
// Scratch (__device__ globals; allocation-free rule)
// ---------------------------------------------------------------------------
__device__ fp16 g_x [M_ * QD_];                       // single fp16 activations
__device__ fp16 g_Wh[NF_ * QD_], g_Wl[NF_ * QD_];     // [Wq ; Wkv] hi/lo
__device__ fp16 g_Ph[QD_ * INNER_], g_Pl[QD_ * INNER_];
__device__ fp16 g_Qh[M_ * INNER_], g_Ql[M_ * INNER_]; // [b*H+h][l][d]
__device__ fp16 g_K [M_ * INNER_];                    // single fp16
__device__ fp16 g_Vh[M_ * INNER_], g_Vl[M_ * INNER_];
__device__ fp16 g_Oh[M_ * INNER_], g_Ol[M_ * INNER_]; // [m][h*64+d]

// ---------------------------------------------------------------------------
// Baseline-PTX helpers
// ---------------------------------------------------------------------------
__device__ __forceinline__ uint32_t smem_u32(const void* p) {
    uint32_t a;
    asm("{ .reg .u64 t; cvta.to.shared.u64 t, %1; cvt.u32.u64 %0, t; }"
        : "=r"(a) : "l"(p));
    return a;
}
__device__ __forceinline__ void cpa16(uint32_t s, const void* g) {
    asm volatile("cp.async.cg.shared.global [%0], [%1], 16;" :: "r"(s), "l"(g));
}
#define CP_COMMIT() asm volatile("cp.async.commit_group;" ::: "memory")
#define CP_WAIT(n)  asm volatile("cp.async.wait_group %0;" :: "n"(n) : "memory")

__device__ __forceinline__ void ldx4(uint32_t r[4], uint32_t a) {
    asm volatile("ldmatrix.sync.aligned.m8n8.x4.shared.b16 {%0,%1,%2,%3}, [%4];"
        : "=r"(r[0]), "=r"(r[1]), "=r"(r[2]), "=r"(r[3]) : "r"(a));
}
__device__ __forceinline__ void ldx4t(uint32_t r[4], uint32_t a) {
    asm volatile("ldmatrix.sync.aligned.m8n8.x4.trans.shared.b16 {%0,%1,%2,%3}, [%4];"
        : "=r"(r[0]), "=r"(r[1]), "=r"(r[2]), "=r"(r[3]) : "r"(a));
}
__device__ __forceinline__ void mma16816(float c[4], const uint32_t a[4],
                                         const uint32_t b[2]) {
    asm volatile(
        "mma.sync.aligned.m16n8k16.row.col.f32.f16.f16.f32 "
        "{%0,%1,%2,%3}, {%4,%5,%6,%7}, {%8,%9}, {%0,%1,%2,%3};"
        : "+f"(c[0]), "+f"(c[1]), "+f"(c[2]), "+f"(c[3])
        : "r"(a[0]), "r"(a[1]), "r"(a[2]), "r"(a[3]), "r"(b[0]), "r"(b[1]));
}
__device__ __forceinline__ uint32_t swz(uint32_t o) { return o ^ ((o >> 3) & 0x70); }

__device__ __forceinline__ float ex2f(float x) {
    float y;
    asm("ex2.approx.f32 %0, %1;" : "=f"(y) : "f"(x));
    return y;
}
__device__ __forceinline__ uint32_t packh2(float x, float y) {
    __half2 h = __float22half2_rn(make_float2(x, y));
    return reinterpret_cast<uint32_t&>(h);
}
__device__ __forceinline__ float2 unpackh2(uint32_t u) {
    return __half22float2(reinterpret_cast<__half2&>(u));
}
__device__ __forceinline__ void store_hl(fp16* dh, fp16* dl, size_t idx,
                                         float v0, float v1) {
    fp16 h0 = __float2half_rn(v0), h1 = __float2half_rn(v1);
    float l0 = v0 - __half2float(h0), l1 = v1 - __half2float(h1);
    __half2 hh = __halves2half2(h0, h1);
    *reinterpret_cast<uint32_t*>(dh + idx) = reinterpret_cast<uint32_t&>(hh);
    *reinterpret_cast<uint32_t*>(dl + idx) = packh2(l0, l1);
}

// ---------------------------------------------------------------------------
// Fused prologue: x cvt + Wq/Wkv split + Wp split, one launch
// ---------------------------------------------------------------------------
__device__ __forceinline__ void split4(const float* __restrict__ s,
                                       fp16* hi, fp16* lo, size_t i4)
{
    float4 v = reinterpret_cast<const float4*>(s)[i4];
    store_hl(hi, lo, i4 * 4,     v.x, v.y);
    store_hl(hi, lo, i4 * 4 + 2, v.z, v.w);
}

__global__ __launch_bounds__(256) void prep_kernel(
    const float* __restrict__ x,  const float* __restrict__ Wq,
    const float* __restrict__ Wkv, const float* __restrict__ Wp)
{
    const int bid = blockIdx.x, tid = threadIdx.x;
    if (bid < 4096) {                       // x: 1M float4 -> fp16
        size_t i = (size_t)bid * 256 + tid;
        float4 v = reinterpret_cast<const float4*>(x)[i];
        uint2 o = make_uint2(packh2(v.x, v.y), packh2(v.z, v.w));
        *reinterpret_cast<uint2*>(g_x + i * 4) = o;
    } else if (bid < 5120) {                // Wq
        size_t i = (size_t)(bid - 4096) * 256 + tid;
        split4(Wq, g_Wh, g_Wl, i);
    } else if (bid < 7168) {                // Wkv, offset 1M elems
        size_t i = (size_t)(bid - 5120) * 256 + tid;
        float4 v = reinterpret_cast<const float4*>(Wkv)[i];
        size_t o = (size_t)INNER_ * QD_ + i * 4;
        store_hl(g_Wh, g_Wl, o,     v.x, v.y);
        store_hl(g_Wh, g_Wl, o + 2, v.z, v.w);
    } else {                                // Wp
        size_t i = (size_t)(bid - 7168) * 256 + tid;
        split4(Wp, g_Ph, g_Pl, i);
    }
}

// ---------------------------------------------------------------------------
// QKV GEMM mainloop: CTA 128m x 64n, 4 warps, warp tile m32 x n64
// Stage: A 16K | Bh 8K | Bl 8K = 32K; 2 stages = 64K -> 3 CTAs/SM (12 warps)
// ---------------------------------------------------------------------------
#define QSTAGE 32768
#define NCH    16

__device__ __forceinline__ void gemm_a1b2_m32(
    const fp16* __restrict__ A,
    const fp16* __restrict__ Bh, const fp16* __restrict__ Bl,
    int m0, int n0, char* smem, float c[16][4])
{
    const int tid = threadIdx.x;
    const int lane = tid & 31, w = tid >> 5;
    const uint32_t sb = smem_u32(smem);

    const int arow = (lane & 7) + ((lane >> 3) & 1) * 8;
    const int acb  = (lane >> 4) * 16;
    const int brow = (lane & 7) + ((lane >> 4) & 1) * 8;
    const int bcb  = ((lane >> 3) & 1) * 16;

    const fp16* Ap  = A  + (size_t)m0 * QD_;
    const fp16* Bhp = Bh + (size_t)n0 * QD_;
    const fp16* Blp = Bl + (size_t)n0 * QD_;

    auto load_stage = [&](int st, int ch) {
        uint32_t base = sb + st * QSTAGE;
        #pragma unroll
        for (int i = 0; i < 8; ++i) {           // A: 128 rows x 128B
            int u = tid + i * 128;
            int row = u >> 3, s7 = u & 7;
            cpa16(base + swz(row * 128 + s7 * 16),
                  Ap + (size_t)row * QD_ + ch * 64 + s7 * 8);
        }
        #pragma unroll
        for (int i = 0; i < 4; ++i) {           // B: 64 rows x 128B, hi+lo
            int u = tid + i * 128;
            int row = u >> 3, s7 = u & 7;
            uint32_t so = swz(row * 128 + s7 * 16);
            cpa16(base + 16384 + so, Bhp + (size_t)row * QD_ + ch * 64 + s7 * 8);
            cpa16(base + 24576 + so, Blp + (size_t)row * QD_ + ch * 64 + s7 * 8);
        }
    };

    load_stage(0, 0); CP_COMMIT();

    for (int ch = 0; ch < NCH; ++ch) {
        CP_WAIT(0);
        __syncthreads();
        if (ch + 1 < NCH) {
            load_stage((ch + 1) & 1, ch + 1);
            CP_COMMIT();
        }

        uint32_t base = sb + (ch & 1) * QSTAGE;
        #pragma unroll
        for (int ks = 0; ks < 4; ++ks) {
            uint32_t a0[4], a1[4];
            ldx4(a0, base + swz((w * 32 +      arow) * 128 + ks * 32 + acb));
            ldx4(a1, base + swz((w * 32 + 16 + arow) * 128 + ks * 32 + acb));
            #pragma unroll
            for (int ng = 0; ng < 4; ++ng) {
                uint32_t bd = base + 16384
                            + swz((ng * 16 + brow) * 128 + ks * 32 + bcb);
                uint32_t bh[4], bl[4];
                ldx4(bh, bd);
                ldx4(bl, bd + 8192);
                mma16816(c[2*ng],       a0, bh);     mma16816(c[2*ng],       a0, bl);
                mma16816(c[2*ng+1],     a0, bh + 2); mma16816(c[2*ng+1],     a0, bl + 2);
                mma16816(c[8 + 2*ng],   a1, bh);     mma16816(c[8 + 2*ng],   a1, bl);
                mma16816(c[8 + 2*ng+1], a1, bh + 2); mma16816(c[8 + 2*ng+1], a1, bl + 2);
            }
        }
    }
}

// ---------------------------------------------------------------------------
// Proj GEMM mainloop (fp16x3, exact): CTA 128m x 64n, 4 warps, m32/warp
// (R14 proven: 70.0us). Stage 48K, 2 stages -> 2 CTAs/SM
// ---------------------------------------------------------------------------
#define GSTAGE 49152

__device__ __forceinline__ void gemm_a2b2_m32(
    const fp16* __restrict__ Ah, const fp16* __restrict__ Al,
    const fp16* __restrict__ Bh, const fp16* __restrict__ Bl,
    int m0, int n0, char* smem, float c[16][4])
{
    const int tid = threadIdx.x;
    const int lane = tid & 31, w = tid >> 5;
    const uint32_t sb = smem_u32(smem);

    const int arow = (lane & 7) + ((lane >> 3) & 1) * 8;
    const int acb  = (lane >> 4) * 16;
    const int brow = (lane & 7) + ((lane >> 4) & 1) * 8;
    const int bcb  = ((lane >> 3) & 1) * 16;

    const fp16* Ahp = Ah + (size_t)m0 * QD_;
    const fp16* Alp = Al + (size_t)m0 * QD_;
    const fp16* Bhp = Bh + (size_t)n0 * QD_;
    const fp16* Blp = Bl + (size_t)n0 * QD_;

    auto load_stage = [&](int st, int ch) {
        uint32_t base = sb + st * GSTAGE;
        #pragma unroll
        for (int i = 0; i < 8; ++i) {           // A: 128 rows, hi+lo
            int u = tid + i * 128;
            int row = u >> 3, s7 = u & 7;
            uint32_t so = swz(row * 128 + s7 * 16);
            cpa16(base + so,         Ahp + (size_t)row * QD_ + ch * 64 + s7 * 8);
            cpa16(base + 16384 + so, Alp + (size_t)row * QD_ + ch * 64 + s7 * 8);
        }
        #pragma unroll
        for (int i = 0; i < 4; ++i) {           // B: 64 rows, hi+lo
            int u = tid + i * 128;
            int row = u >> 3, s7 = u & 7;
            uint32_t so = swz(row * 128 + s7 * 16);
            cpa16(base + 32768 + so, Bhp + (size_t)row * QD_ + ch * 64 + s7 * 8);
            cpa16(base + 40960 + so, Blp + (size_t)row * QD_ + ch * 64 + s7 * 8);
        }
    };

    load_stage(0, 0); CP_COMMIT();

    for (int ch = 0; ch < NCH; ++ch) {
        CP_WAIT(0);
        __syncthreads();
        if (ch + 1 < NCH) {
            load_stage((ch + 1) & 1, ch + 1);
            CP_COMMIT();
        }

        uint32_t base = sb + (ch & 1) * GSTAGE;
        #pragma unroll
        for (int ks = 0; ks < 4; ++ks) {
            uint32_t ah0[4], ah1[4], al0[4], al1[4];
            uint32_t ad0 = base + swz((w * 32 +      arow) * 128 + ks * 32 + acb);
            uint32_t ad1 = base + swz((w * 32 + 16 + arow) * 128 + ks * 32 + acb);
            ldx4(ah0, ad0); ldx4(al0, ad0 + 16384);
            ldx4(ah1, ad1); ldx4(al1, ad1 + 16384);
            #pragma unroll
            for (int ng = 0; ng < 4; ++ng) {
                uint32_t bd = base + 32768
                            + swz((ng * 16 + brow) * 128 + ks * 32 + bcb);
                uint32_t bh[4], bl[4];
                ldx4(bh, bd);
                ldx4(bl, bd + 8192);
                mma16816(c[2*ng],       ah0, bh);     mma16816(c[2*ng],       ah0, bl);
                mma16816(c[2*ng],       al0, bh);
                mma16816(c[2*ng+1],     ah0, bh + 2); mma16816(c[2*ng+1],     ah0, bl + 2);
                mma16816(c[2*ng+1],     al0, bh + 2);
                mma16816(c[8 + 2*ng],   ah1, bh);     mma16816(c[8 + 2*ng],   ah1, bl);
                mma16816(c[8 + 2*ng],   al1, bh);
                mma16816(c[8 + 2*ng+1], ah1, bh + 2); mma16816(c[8 + 2*ng+1], ah1, bl + 2);
                mma16816(c[8 + 2*ng+1], al1, bh + 2);
            }
        }
    }
}

// ---------------------------------------------------------------------------
// QKV projection GEMM + RMSNorm + RoPE
//   grid = (M_/128, NF_/64), 128 threads, 3 CTAs/SM
// ---------------------------------------------------------------------------
__global__ __launch_bounds__(128, 3) void qkv_mma(
    const float* __restrict__ pe,
    const float* __restrict__ qsc, const float* __restrict__ ksc)
{
    extern __shared__ char smem[];
    const int m0 = blockIdx.x * 128, n0 = blockIdx.y * 64;
    float c[16][4];
    #pragma unroll
    for (int j = 0; j < 16; ++j)
        #pragma unroll
        for (int k = 0; k < 4; ++k) c[j][k] = 0.f;

    gemm_a1b2_m32(g_x, g_Wh, g_Wl, m0, n0, smem, c);

    const int tid = threadIdx.x, lane = tid & 31, w = tid >> 5;
    const int tq = lane & 3, g = lane >> 2;

    const int kind = n0 >> 10;               // 0:Q 1:K 2:V
    const int h = (n0 & 1023) >> 6;
    const float* sc = (kind == 0) ? qsc : ksc;
    const float qm = (kind == 0) ? 0.125f * 1.4426950408889634f : 1.f;

    #pragma unroll
    for (int mi = 0; mi < 2; ++mi)
        #pragma unroll
        for (int half_ = 0; half_ < 2; ++half_) {
            const int m = m0 + w * 32 + mi * 16 + g + half_ * 8;
            const int b = m >> 11, l = m & 2047;
            const size_t obase = ((size_t)(b * H_ + h) * L_ + l) * 64;
            float (*cc)[4] = c + mi * 8;

            if (kind == 2) {
                #pragma unroll
                for (int ni = 0; ni < 8; ++ni) {
                    int d0 = ni * 8 + tq * 2;
                    store_hl(g_Vh, g_Vl, obase + d0,
                             cc[ni][half_ * 2], cc[ni][half_ * 2 + 1]);
                }
            } else {
                float ss = 0.f;
                #pragma unroll
                for (int ni = 0; ni < 8; ++ni) {
                    float v0 = cc[ni][half_ * 2], v1 = cc[ni][half_ * 2 + 1];
                    ss = fmaf(v0, v0, fmaf(v1, v1, ss));
                }
                ss += __shfl_xor_sync(0xffffffffu, ss, 1);
                ss += __shfl_xor_sync(0xffffffffu, ss, 2);
                const float rr = rsqrtf(ss * (1.f / 64.f) + 1e-6f);
                const float* pel = pe + (size_t)l * 128;
                #pragma unroll
                for (int ni = 0; ni < 8; ++ni) {
                    int d0 = ni * 8 + tq * 2;
                    float v0 = cc[ni][half_ * 2]     * rr * sc[d0];
                    float v1 = cc[ni][half_ * 2 + 1] * rr * sc[d0 + 1];
                    float4 p = *reinterpret_cast<const float4*>(pel + (d0 >> 1) * 4);
                    float o0 = (p.x * v0 + p.y * v1) * qm;
                    float o1 = (p.z * v0 + p.w * v1) * qm;
                    if (kind == 0) store_hl(g_Qh, g_Ql, obase + d0, o0, o1);
                    else *reinterpret_cast<uint32_t*>(g_K + obase + d0) = packh2(o0, o1);
                }
            }
        }
}

// ---------------------------------------------------------------------------
// Output projection GEMM (exact fp16x3, m32 warps) + bias  (R14 proven)
//   grid = (M_/128, QD_/64), 128 threads
// ---------------------------------------------------------------------------
__global__ __launch_bounds__(128, 2) void proj_mma(
    const float* __restrict__ bp, float* __restrict__ out)
{
    extern __shared__ char smem[];
    const int m0 = blockIdx.x * 128, n0 = blockIdx.y * 64;
    float c[16][4];
    #pragma unroll
    for (int j = 0; j < 16; ++j)
        #pragma unroll
        for (int k = 0; k < 4; ++k) c[j][k] = 0.f;

    gemm_a2b2_m32(g_Oh, g_Ol, g_Ph, g_Pl, m0, n0, smem, c);

    const int tid = threadIdx.x, lane = tid & 31, w = tid >> 5;
    const int tq = lane & 3, g = lane >> 2;

    #pragma unroll
    for (int mi = 0; mi < 2; ++mi)
        #pragma unroll
        for (int half_ = 0; half_ < 2; ++half_) {
            const int m = m0 + w * 32 + mi * 16 + g + half_ * 8;
            float (*cc)[4] = c + mi * 8;
            #pragma unroll
            for (int ni = 0; ni < 8; ++ni) {
                int col = n0 + ni * 8 + tq * 2;
                float2 bv = *reinterpret_cast<const float2*>(bp + col);
                float2 o = make_float2(cc[ni][half_ * 2]     + bv.x,
                                       cc[ni][half_ * 2 + 1] + bv.y);
                *reinterpret_cast<float2*>(out + (size_t)m * QD_ + col) = o;
            }
        }
}

// ---------------------------------------------------------------------------
// Flash attention (R11/R13 proven shape): 64 q-rows, 128 threads, 3 CTAs/SM
//   S = (Qh+Ql)·K ; O = P̂·(Vh+Vl), exp2-domain online softmax
//   smem: Qh 8K | Ql 8K | 2 stages x (K 8K | Vh 8K | Vl 8K) = 64K
// ---------------------------------------------------------------------------
#define ASTAGE 24576
#define ASMEM  (16384 + 2 * ASTAGE)
#define NIT    32

__global__ __launch_bounds__(128, 3) void attn_mma()
{
    extern __shared__ char smem[];
    const int tid = threadIdx.x, lane = tid & 31, w = tid >> 5;
    const int by = blockIdx.y;
    const int q0 = blockIdx.x * 64;
    const uint32_t sb = smem_u32(smem);

    const fp16* Qhp = g_Qh + ((size_t)by * L_ + q0) * 64;
    const fp16* Qlp = g_Ql + ((size_t)by * L_ + q0) * 64;
    const fp16* Kp  = g_K  + (size_t)by * L_ * 64;
    const fp16* Vhp = g_Vh + (size_t)by * L_ * 64;
    const fp16* Vlp = g_Vl + (size_t)by * L_ * 64;

    const int tq = lane & 3, g = lane >> 2;
    const int arow = (lane & 7) + ((lane >> 3) & 1) * 8;
    const int acb  = (lane >> 4) * 16;
    const int brow = (lane & 7) + ((lane >> 4) & 1) * 8;
    const int bcb  = ((lane >> 3) & 1) * 16;

    auto load_kv = [&](int st, int kt) {
        uint32_t base = sb + 16384 + st * ASTAGE;
        const fp16* srcs[3] = { Kp, Vhp, Vlp };
        #pragma unroll
        for (int mtx = 0; mtx < 3; ++mtx)
            #pragma unroll
            for (int i = 0; i < 4; ++i) {
                int u = tid + i * 128;
                int row = u >> 3, s7 = u & 7;
                cpa16(base + mtx * 8192 + swz(row * 128 + s7 * 16),
                      srcs[mtx] + (size_t)(kt * 64 + row) * 64 + s7 * 8);
            }
    };

    #pragma unroll
    for (int i = 0; i < 4; ++i) {
        int u = tid + i * 128;
        int row = u >> 3, s7 = u & 7;
        uint32_t so = swz(row * 128 + s7 * 16);
        cpa16(sb +        so, Qhp + (size_t)row * 64 + s7 * 8);
        cpa16(sb + 8192 + so, Qlp + (size_t)row * 64 + s7 * 8);
    }
    load_kv(0, 0); CP_COMMIT();

    float o[8][4];
    #pragma unroll
    for (int i = 0; i < 8; ++i)
        #pragma unroll
        for (int j = 0; j < 4; ++j) o[i][j] = 0.f;
    float mr0 = -1e30f, mr1 = -1e30f, lr0 = 0.f, lr1 = 0.f;
    uint32_t qhf[4][4], qlf[4][4];

    for (int it = 0; it < NIT; ++it) {
        CP_WAIT(0);
        __syncthreads();
        if (it + 1 < NIT) {
            load_kv((it + 1) & 1, it + 1);
            CP_COMMIT();
        }

        if (it == 0) {
            #pragma unroll
            for (int ks = 0; ks < 4; ++ks) {
                uint32_t ad = sb + swz((w * 16 + arow) * 128 + ks * 32 + acb);
                ldx4(qhf[ks], ad);
                ldx4(qlf[ks], ad + 8192);
            }
        }

        const uint32_t kb = sb + 16384 + (it & 1) * ASTAGE;

        // ---- S = (Qh+Ql) K^T (log2 domain) ----
        float s[8][4];
        #pragma unroll
        for (int i = 0; i < 8; ++i)
            #pragma unroll
            for (int j = 0; j < 4; ++j) s[i][j] = 0.f;

        #pragma unroll
        for (int ks = 0; ks < 4; ++ks)
            #pragma unroll
            for (int ng = 0; ng < 4; ++ng) {
                uint32_t kd = kb + swz((ng * 16 + brow) * 128 + ks * 32 + bcb);
                uint32_t kh[4];
                ldx4(kh, kd);
                mma16816(s[2*ng],   qhf[ks], kh);
                mma16816(s[2*ng],   qlf[ks], kh);
                mma16816(s[2*ng+1], qhf[ks], kh + 2);
                mma16816(s[2*ng+1], qlf[ks], kh + 2);
            }

        // ---- online softmax (exp2 domain, consistent quantized sums) ----
        float mx0 = -1e30f, mx1 = -1e30f;
        #pragma unroll
        for (int ni = 0; ni < 8; ++ni) {
            mx0 = fmaxf(mx0, fmaxf(s[ni][0], s[ni][1]));
            mx1 = fmaxf(mx1, fmaxf(s[ni][2], s[ni][3]));
        }
        mx0 = fmaxf(mx0, __shfl_xor_sync(0xffffffffu, mx0, 1));
        mx0 = fmaxf(mx0, __shfl_xor_sync(0xffffffffu, mx0, 2));
        mx1 = fmaxf(mx1, __shfl_xor_sync(0xffffffffu, mx1, 1));
        mx1 = fmaxf(mx1, __shfl_xor_sync(0xffffffffu, mx1, 2));
        const float mn0 = fmaxf(mr0, mx0), mn1 = fmaxf(mr1, mx1);
        const float cr0 = ex2f(mr0 - mn0), cr1 = ex2f(mr1 - mn1);
        mr0 = mn0; mr1 = mn1;

        float sum0 = 0.f, sum1 = 0.f;
        uint32_t ph01[8], ph23[8];
        #pragma unroll
        for (int ni = 0; ni < 8; ++ni) {
            float p0 = ex2f(s[ni][0] - mn0), p1 = ex2f(s[ni][1] - mn0);
            float p2 = ex2f(s[ni][2] - mn1), p3 = ex2f(s[ni][3] - mn1);
            ph01[ni] = packh2(p0, p1);
            ph23[ni] = packh2(p2, p3);
            float2 q01 = unpackh2(ph01[ni]);
            float2 q23 = unpackh2(ph23[ni]);
            sum0 += q01.x + q01.y;
            sum1 += q23.x + q23.y;
        }
        sum0 += __shfl_xor_sync(0xffffffffu, sum0, 1);
        sum0 += __shfl_xor_sync(0xffffffffu, sum0, 2);
        sum1 += __shfl_xor_sync(0xffffffffu, sum1, 1);
        sum1 += __shfl_xor_sync(0xffffffffu, sum1, 2);
        lr0 = lr0 * cr0 + sum0;
        lr1 = lr1 * cr1 + sum1;
        #pragma unroll
        for (int ni = 0; ni < 8; ++ni) {
            o[ni][0] *= cr0; o[ni][1] *= cr0;
            o[ni][2] *= cr1; o[ni][3] *= cr1;
        }

        // ---- O += P̂ (Vh+Vl) ----
        const uint32_t vb = kb + 8192;
        #pragma unroll
        for (int kk = 0; kk < 4; ++kk) {
            uint32_t pa[4] = { ph01[2*kk], ph23[2*kk], ph01[2*kk+1], ph23[2*kk+1] };
            #pragma unroll
            for (int dg = 0; dg < 4; ++dg) {
                uint32_t vd = vb + swz((kk * 16 + arow) * 128 + dg * 32 + acb);
                uint32_t vh[4], vl[4];
                ldx4t(vh, vd);
                ldx4t(vl, vd + 8192);
                mma16816(o[2*dg],   pa, vh);
                mma16816(o[2*dg],   pa, vl);
                mma16816(o[2*dg+1], pa, vh + 2);
                mma16816(o[2*dg+1], pa, vl + 2);
            }
        }
    }

    // ---- epilogue ----
    const float i0 = 1.f / lr0, i1 = 1.f / lr1;
    const int b = by >> 4, h = by & 15;
    #pragma unroll
    for (int half_ = 0; half_ < 2; ++half_) {
        const int l = q0 + w * 16 + g + half_ * 8;
        const size_t mbase = ((size_t)(b * L_ + l)) * INNER_ + h * 64;
        const float inv = half_ ? i1 : i0;
        #pragma unroll
        for (int ni = 0; ni < 8; ++ni) {
            int d0 = ni * 8 + tq * 2;
            store_hl(g_Oh, g_Ol, mbase + d0,
                     o[ni][half_ * 2] * inv, o[ni][half_ * 2 + 1] * inv);
        }
    }
}

// ---------------------------------------------------------------------------
extern "C" void kernel_launch(void* const* d_in, const int* in_sizes, int n_in,
                              void* d_out, int out_size)
{
    const float* x   = (const float*)d_in[0];
    const float* pe  = (const float*)d_in[1];
    const float* Wq  = (const float*)d_in[2];
    const float* Wkv = (const float*)d_in[3];
    const float* Wp  = (const float*)d_in[4];
    const float* bp  = (const float*)d_in[5];
    const float* qs  = (const float*)d_in[6];
    const float* ks  = (const float*)d_in[7];
    float* out = (float*)d_out;

    cudaFuncSetAttribute(qkv_mma,  cudaFuncAttributeMaxDynamicSharedMemorySize, 2 * QSTAGE);
    cudaFuncSetAttribute(proj_mma, cudaFuncAttributeMaxDynamicSharedMemorySize, 2 * GSTAGE);
    cudaFuncSetAttribute(attn_mma, cudaFuncAttributeMaxDynamicSharedMemorySize, ASMEM);

    prep_kernel<<<8192, 256>>>(x, Wq, Wkv, Wp);
    qkv_mma<<<dim3(M_ / 128, NF_ / 64), 128, 2 * QSTAGE>>>(pe, qs, ks);
    attn_mma<<<dim3(L_ / 64, B_ * H_), 128, ASMEM>>>();
    proj_mma<<<dim3(M_ / 128, QD_ / 64), 128, 2 * GSTAGE>>>(bp, out);
}